// round 11
// baseline (speedup 1.0000x reference)
#include <cuda_runtime.h>
#include <math.h>
#include <stdint.h>

// IterNormRotation: X (32,512,56,56) fp32, rot (1,512,512) fp32, T=10.
//   S = X Xᵀ (Gram over m=B*H*W) via tf32 MMA, sum_c = channel sums
//   Sigma = eps I + S/m - mu muᵀ ; rTr = 1/tr ; SN = Sigma*rTr ; P = I
//   10x NS: P = 1.5P - 0.5 (P@P)@(P@SN)   (fp32 SIMT, dual-output kernel)
//   M = sqrt(rTr) * rot @ P ; bias = M@mu
//   out = M @ X - bias  via tf32 MMA

#define Cc   512
#define Bb   32
#define HWs  3136
#define MTOTf 100352.0f
#define EPSf 1e-5f
#define NS_ITERS 10

#define GP 36     // pitch for [row][k] tiles (k=32)
#define BP 136    // pitch for [k][n] tiles (n=128)

__device__ float g_S [Cc*Cc];
__device__ float g_SN[Cc*Cc];
__device__ float g_P [Cc*Cc];
__device__ float g_T1[Cc*Cc];
__device__ float g_T2[Cc*Cc];
__device__ float g_M [Cc*Cc];
__device__ float g_sum [Cc];
__device__ float g_mean[Cc];
__device__ float g_bias[Cc];
__device__ float g_scal[2];   // [0]=rTr, [1]=sqrt(rTr)

// ---------------------------------------------------------------- helpers
__device__ __forceinline__ uint32_t f2tf(float f) {
    uint32_t u; asm("cvt.rna.tf32.f32 %0, %1;" : "=r"(u) : "f"(f)); return u;
}

__device__ __forceinline__ void mma8(float* d, const uint32_t* a, const uint32_t* b) {
    asm volatile(
        "mma.sync.aligned.m16n8k8.row.col.f32.tf32.tf32.f32 "
        "{%0,%1,%2,%3}, {%4,%5,%6,%7}, {%8,%9}, {%0,%1,%2,%3};\n"
        : "+f"(d[0]), "+f"(d[1]), "+f"(d[2]), "+f"(d[3])
        : "r"(a[0]), "r"(a[1]), "r"(a[2]), "r"(a[3]), "r"(b[0]), "r"(b[1]));
}

// ---------------------------------------------------------------- zero
__global__ void k_zero() {
    int idx = blockIdx.x * blockDim.x + threadIdx.x;
    if (idx < Cc*Cc) g_S[idx] = 0.f;
    if (idx < Cc)    g_sum[idx] = 0.f;
}

// ---------------------------------------------------------------- channel sums
__global__ void k_sums(const float* __restrict__ X) {
    int c = blockIdx.x, b = blockIdx.y;
    const float4* p = (const float4*)(X + ((size_t)b * Cc + c) * HWs);
    float s = 0.f;
    for (int i = threadIdx.x; i < HWs/4; i += 128) {
        float4 v = p[i];
        s += (v.x + v.y) + (v.z + v.w);
    }
    #pragma unroll
    for (int o = 16; o > 0; o >>= 1) s += __shfl_down_sync(0xffffffffu, s, o);
    __shared__ float sm[4];
    if ((threadIdx.x & 31) == 0) sm[threadIdx.x >> 5] = s;
    __syncthreads();
    if (threadIdx.x == 0) atomicAdd(&g_sum[c], sm[0] + sm[1] + sm[2] + sm[3]);
}

// ---------------------------------------------------------------- Gram (tf32 MMA)
// 128x128 tile per (pair, batch), BK=32, 8 warps of 64x32 warp-tiles.
__global__ void __launch_bounds__(256, 2) k_gram(const float* __restrict__ X) {
    int p = blockIdx.x;
    int it = 0, rem = p;
    while (rem >= 4 - it) { rem -= 4 - it; it++; }
    int jt = it + rem;
    int b  = blockIdx.y;

    int i0 = it * 128, j0 = jt * 128;
    const float* Xb = X + (size_t)b * Cc * HWs;

    __shared__ uint32_t As[128 * GP];   // [row 0..127][k 0..31]
    __shared__ uint32_t Bs[128 * GP];

    int tid  = threadIdx.x;
    int lane = tid & 31, warp = tid >> 5;
    int g = lane >> 2, tig = lane & 3;
    int wm = (warp >> 2) * 64;     // warp row base (2 rows of warps)
    int wn = (warp & 3) * 32;      // warp col base (4 cols of warps)

    float acc[4][4][4];
    #pragma unroll
    for (int mt = 0; mt < 4; mt++)
        #pragma unroll
        for (int nt = 0; nt < 4; nt++)
            #pragma unroll
            for (int i = 0; i < 4; i++) acc[mt][nt][i] = 0.f;

    for (int k0 = 0; k0 < HWs; k0 += 32) {
        #pragma unroll
        for (int l = 0; l < 4; l++) {
            int e   = tid + l * 256;          // 1024 float4 slots per tile
            int row = e >> 3;
            int kq  = (e & 7) * 4;
            float4 va = *(const float4*)(Xb + (size_t)(i0 + row) * HWs + k0 + kq);
            *(uint4*)&As[row * GP + kq] =
                make_uint4(f2tf(va.x), f2tf(va.y), f2tf(va.z), f2tf(va.w));
            float4 vb = *(const float4*)(Xb + (size_t)(j0 + row) * HWs + k0 + kq);
            *(uint4*)&Bs[row * GP + kq] =
                make_uint4(f2tf(vb.x), f2tf(vb.y), f2tf(vb.z), f2tf(vb.w));
        }
        __syncthreads();

        #pragma unroll
        for (int ks = 0; ks < 32; ks += 8) {
            uint32_t af[4][4], bf[4][2];
            #pragma unroll
            for (int mt = 0; mt < 4; mt++) {
                int r = wm + mt * 16 + g;
                af[mt][0] = As[r       * GP + ks + tig];
                af[mt][1] = As[(r + 8) * GP + ks + tig];
                af[mt][2] = As[r       * GP + ks + tig + 4];
                af[mt][3] = As[(r + 8) * GP + ks + tig + 4];
            }
            #pragma unroll
            for (int nt = 0; nt < 4; nt++) {
                int c = wn + nt * 8 + g;
                bf[nt][0] = Bs[c * GP + ks + tig];
                bf[nt][1] = Bs[c * GP + ks + tig + 4];
            }
            #pragma unroll
            for (int mt = 0; mt < 4; mt++)
                #pragma unroll
                for (int nt = 0; nt < 4; nt++)
                    mma8(acc[mt][nt], af[mt], bf[nt]);
        }
        __syncthreads();
    }

    bool mirror = (it != jt);
    #pragma unroll
    for (int mt = 0; mt < 4; mt++) {
        int m_ = wm + mt * 16 + g;
        #pragma unroll
        for (int nt = 0; nt < 4; nt++) {
            int n_ = wn + nt * 8 + 2 * tig;
            int gi0 = i0 + m_, gi1 = gi0 + 8;
            int gj0 = j0 + n_, gj1 = gj0 + 1;
            atomicAdd(&g_S[gi0 * Cc + gj0], acc[mt][nt][0]);
            atomicAdd(&g_S[gi0 * Cc + gj1], acc[mt][nt][1]);
            atomicAdd(&g_S[gi1 * Cc + gj0], acc[mt][nt][2]);
            atomicAdd(&g_S[gi1 * Cc + gj1], acc[mt][nt][3]);
            if (mirror) {
                atomicAdd(&g_S[gj0 * Cc + gi0], acc[mt][nt][0]);
                atomicAdd(&g_S[gj1 * Cc + gi0], acc[mt][nt][1]);
                atomicAdd(&g_S[gj0 * Cc + gi1], acc[mt][nt][2]);
                atomicAdd(&g_S[gj1 * Cc + gi1], acc[mt][nt][3]);
            }
        }
    }
}

// ---------------------------------------------------------------- prep
__global__ void k_prep1() {   // 1 block, 512 threads
    int c = threadIdx.x;
    float mean = g_sum[c] * (1.0f / MTOTf);
    g_mean[c] = mean;
    float t = EPSf + g_S[c * Cc + c] * (1.0f / MTOTf) - mean * mean;
    __shared__ float red[16];
    #pragma unroll
    for (int o = 16; o > 0; o >>= 1) t += __shfl_down_sync(0xffffffffu, t, o);
    if ((c & 31) == 0) red[c >> 5] = t;
    __syncthreads();
    if (c < 16) {
        float v = red[c];
        #pragma unroll
        for (int o = 8; o > 0; o >>= 1) v += __shfl_down_sync(0x0000ffffu, v, o);
        if (c == 0) {
            float rtr = 1.0f / v;
            g_scal[0] = rtr;
            g_scal[1] = sqrtf(rtr);
        }
    }
}

__global__ void k_prep2() {   // grid 1024 x 256
    int idx = blockIdx.x * 256 + threadIdx.x;
    int i = idx >> 9, j = idx & 511;
    float v = g_S[idx] * (1.0f / MTOTf) - g_mean[i] * g_mean[j];
    if (i == j) v += EPSf;
    g_SN[idx] = v * g_scal[0];
    g_P[idx]  = (i == j) ? 1.0f : 0.0f;
}

// ---------------------------------------------------------------- 512^3 fp32 GEMM body
__device__ __forceinline__ void gemm512_body(
    const float* __restrict__ A, const float* __restrict__ Bm,
    const float* __restrict__ Cin, float* __restrict__ D,
    float alpha, float beta, const float* __restrict__ alpha_dev,
    int i0, int j0)
{
    __shared__ float As[32][68];
    __shared__ float Bs[32][68];

    float acc[4][4];
    #pragma unroll
    for (int r = 0; r < 4; r++)
        #pragma unroll
        for (int c = 0; c < 4; c++) acc[r][c] = 0.f;

    int tid = threadIdx.x;
    int tx4 = (tid & 15) * 4;
    int ty4 = (tid >> 4) * 4;

    for (int k0 = 0; k0 < Cc; k0 += 32) {
        #pragma unroll
        for (int l = 0; l < 2; l++) {
            int idx = tid + l * 256;
            int row = idx >> 3;
            int kq  = (idx & 7) * 4;
            float4 va = *(const float4*)(A + (size_t)(i0 + row) * Cc + k0 + kq);
            As[kq + 0][row] = va.x; As[kq + 1][row] = va.y;
            As[kq + 2][row] = va.z; As[kq + 3][row] = va.w;
            int krow = idx >> 4;
            int cq   = (idx & 15) * 4;
            *(float4*)&Bs[krow][cq] =
                *(const float4*)(Bm + (size_t)(k0 + krow) * Cc + j0 + cq);
        }
        __syncthreads();
        #pragma unroll
        for (int kk = 0; kk < 32; kk++) {
            float4 av = *(const float4*)&As[kk][ty4];
            float4 bv = *(const float4*)&Bs[kk][tx4];
            float ar[4] = {av.x, av.y, av.z, av.w};
            float br[4] = {bv.x, bv.y, bv.z, bv.w};
            #pragma unroll
            for (int r = 0; r < 4; r++)
                #pragma unroll
                for (int c = 0; c < 4; c++)
                    acc[r][c] += ar[r] * br[c];
        }
        __syncthreads();
    }

    float al = alpha;
    if (alpha_dev) al *= *alpha_dev;
    #pragma unroll
    for (int r = 0; r < 4; r++) {
        int gi = i0 + ty4 + r;
        float4 v;
        v.x = al * acc[r][0]; v.y = al * acc[r][1];
        v.z = al * acc[r][2]; v.w = al * acc[r][3];
        if (Cin) {
            float4 ci = *(const float4*)(Cin + (size_t)gi * Cc + j0 + tx4);
            v.x += beta * ci.x; v.y += beta * ci.y;
            v.z += beta * ci.z; v.w += beta * ci.w;
        }
        *(float4*)(D + (size_t)gi * Cc + j0 + tx4) = v;
    }
}

__global__ void __launch_bounds__(256) k_gemm512(
    const float* __restrict__ A, const float* __restrict__ Bm,
    const float* __restrict__ Cin, float* __restrict__ D,
    float alpha, float beta, const float* __restrict__ alpha_dev)
{
    gemm512_body(A, Bm, Cin, D, alpha, beta, alpha_dev,
                 blockIdx.y * 64, blockIdx.x * 64);
}

// dual: z=0 -> D0 = A@B0, z=1 -> D1 = A@B1  (grid 8,8,2)
__global__ void __launch_bounds__(256) k_gemm512_dual(
    const float* __restrict__ A,
    const float* __restrict__ B0, const float* __restrict__ B1,
    float* __restrict__ D0, float* __restrict__ D1)
{
    gemm512_body(A, blockIdx.z ? B1 : B0, nullptr, blockIdx.z ? D1 : D0,
                 1.0f, 0.0f, nullptr, blockIdx.y * 64, blockIdx.x * 64);
}

// ---------------------------------------------------------------- bias = M @ mean
__global__ void k_bias() {   // grid 64 x 256
    int d = blockIdx.x * 8 + (threadIdx.x >> 5);
    int lane = threadIdx.x & 31;
    float s = 0.f;
    for (int c = lane; c < Cc; c += 32) s += g_M[d * Cc + c] * g_mean[c];
    #pragma unroll
    for (int o = 16; o > 0; o >>= 1) s += __shfl_down_sync(0xffffffffu, s, o);
    if (lane == 0) g_bias[d] = s;
}

// ---------------------------------------------------------------- out = M @ X - bias (tf32 MMA)
// per-batch 512x3136: 128x128 tiles, BK=32, 8 warps of 64x32.
__global__ void __launch_bounds__(256, 2) k_out(const float* __restrict__ X,
                                                float* __restrict__ Out)
{
    int j0 = blockIdx.x * 128;   // hw tile (25, last partial)
    int i0 = blockIdx.y * 128;   // d tile (4)
    int b  = blockIdx.z;

    const float* Xb = X + (size_t)b * Cc * HWs;

    __shared__ uint32_t As[128 * GP];   // M tile  [m][k]
    __shared__ uint32_t Bs[32 * BP];    // X tile  [k][n]

    int tid  = threadIdx.x;
    int lane = tid & 31, warp = tid >> 5;
    int g = lane >> 2, tig = lane & 3;
    int wm = (warp >> 2) * 64;
    int wn = (warp & 3) * 32;

    float acc[4][4][4];
    #pragma unroll
    for (int mt = 0; mt < 4; mt++)
        #pragma unroll
        for (int nt = 0; nt < 4; nt++)
            #pragma unroll
            for (int i = 0; i < 4; i++) acc[mt][nt][i] = 0.f;

    for (int k0 = 0; k0 < Cc; k0 += 32) {
        // A tile: 128 rows x 8 kquads
        #pragma unroll
        for (int l = 0; l < 4; l++) {
            int e   = tid + l * 256;
            int row = e >> 3;
            int kq  = (e & 7) * 4;
            float4 v = *(const float4*)(g_M + (size_t)(i0 + row) * Cc + k0 + kq);
            *(uint4*)&As[row * GP + kq] =
                make_uint4(f2tf(v.x), f2tf(v.y), f2tf(v.z), f2tf(v.w));
        }
        // B tile: 32 krows x 32 nquads
        #pragma unroll
        for (int l = 0; l < 4; l++) {
            int e  = tid + l * 256;
            int kr = e >> 5;
            int nq = (e & 31) * 4;
            int hw = j0 + nq;
            float4 v = make_float4(0.f, 0.f, 0.f, 0.f);
            if (hw < HWs)
                v = *(const float4*)(Xb + (size_t)(k0 + kr) * HWs + hw);
            *(uint4*)&Bs[kr * BP + nq] =
                make_uint4(f2tf(v.x), f2tf(v.y), f2tf(v.z), f2tf(v.w));
        }
        __syncthreads();

        #pragma unroll
        for (int ks = 0; ks < 32; ks += 8) {
            uint32_t af[4][4], bf[4][2];
            #pragma unroll
            for (int mt = 0; mt < 4; mt++) {
                int r = wm + mt * 16 + g;
                af[mt][0] = As[r       * GP + ks + tig];
                af[mt][1] = As[(r + 8) * GP + ks + tig];
                af[mt][2] = As[r       * GP + ks + tig + 4];
                af[mt][3] = As[(r + 8) * GP + ks + tig + 4];
            }
            #pragma unroll
            for (int nt = 0; nt < 4; nt++) {
                int c = wn + nt * 8 + g;
                bf[nt][0] = Bs[(ks + tig)     * BP + c];
                bf[nt][1] = Bs[(ks + tig + 4) * BP + c];
            }
            #pragma unroll
            for (int mt = 0; mt < 4; mt++)
                #pragma unroll
                for (int nt = 0; nt < 4; nt++)
                    mma8(acc[mt][nt], af[mt], bf[nt]);
        }
        __syncthreads();
    }

    #pragma unroll
    for (int mt = 0; mt < 4; mt++) {
        int m_  = wm + mt * 16 + g;
        int gi0 = i0 + m_;
        int gi1 = gi0 + 8;
        float bv0 = g_bias[gi0];
        float bv1 = g_bias[gi1];
        float* orow0 = Out + ((size_t)b * Cc + gi0) * HWs;
        float* orow1 = Out + ((size_t)b * Cc + gi1) * HWs;
        #pragma unroll
        for (int nt = 0; nt < 4; nt++) {
            int col = j0 + wn + nt * 8 + 2 * tig;
            if (col < HWs) {
                float2 v0 = make_float2(acc[mt][nt][0] - bv0, acc[mt][nt][1] - bv0);
                float2 v1 = make_float2(acc[mt][nt][2] - bv1, acc[mt][nt][3] - bv1);
                *(float2*)(orow0 + col) = v0;
                *(float2*)(orow1 + col) = v1;
            }
        }
    }
}

// ---------------------------------------------------------------- launch
extern "C" void kernel_launch(void* const* d_in, const int* in_sizes, int n_in,
                              void* d_out, int out_size)
{
    const float* X   = (const float*)d_in[0];
    const float* rot = (const float*)d_in[1];
    float* Out = (float*)d_out;

    float *pP, *pSN, *pT1, *pT2, *pM, *pScal;
    cudaGetSymbolAddress((void**)&pP,    g_P);
    cudaGetSymbolAddress((void**)&pSN,   g_SN);
    cudaGetSymbolAddress((void**)&pT1,   g_T1);
    cudaGetSymbolAddress((void**)&pT2,   g_T2);
    cudaGetSymbolAddress((void**)&pM,    g_M);
    cudaGetSymbolAddress((void**)&pScal, g_scal);

    k_zero<<<(Cc*Cc + 255) / 256, 256>>>();
    k_sums<<<dim3(Cc, Bb), 128>>>(X);
    k_gram<<<dim3(10, Bb), 256>>>(X);
    k_prep1<<<1, 512>>>();
    k_prep2<<<(Cc*Cc) / 256, 256>>>();

    for (int t = 0; t < NS_ITERS; t++) {
        // T1 = P@P, T2 = P@SN in one launch
        k_gemm512_dual<<<dim3(8, 8, 2), 256>>>(pP, pP, pSN, pT1, pT2);
        // P = 1.5P - 0.5 T1@T2
        k_gemm512<<<dim3(8, 8), 256>>>(pT1, pT2, pP, pP, -0.5f, 1.5f, nullptr);
    }

    // M = sqrt(rTr) * rot @ P
    k_gemm512<<<dim3(8, 8), 256>>>(rot, pP, nullptr, pM, 1.0f, 0.0f, pScal + 1);
    k_bias<<<64, 256>>>();
    k_out<<<dim3(25, 4, Bb), 256>>>(X, Out);
}

// round 12
// speedup vs baseline: 1.4759x; 1.4759x over previous
#include <cuda_runtime.h>
#include <math.h>
#include <stdint.h>

// IterNormRotation: X (32,512,56,56) fp32, rot (1,512,512) fp32, T=10.
//   S = X Xᵀ (Gram over m=B*H*W) via tf32 MMA, sum_c = channel sums
//   Sigma = eps I + S/m - mu muᵀ ; rTr = 1/tr ; SN = Sigma*rTr ; P = I
//   10x NS: P = 1.5P - 0.5 (P@P)@(P@SN)   (fp32 SIMT, dual-output kernel)
//   M = sqrt(rTr) * rot @ P ; bias = M@mu
//   out = M @ X - bias  via tf32 MMA

#define Cc   512
#define Bb   32
#define HWs  3136
#define MTOTf 100352.0f
#define EPSf 1e-5f
#define NS_ITERS 10

#define GP 36     // pitch for [row][k] tiles (k=32)
#define BP 136    // pitch for [k][n] tiles (n=128)

__device__ float g_S [Cc*Cc];
__device__ float g_SN[Cc*Cc];
__device__ float g_P [Cc*Cc];
__device__ float g_T1[Cc*Cc];
__device__ float g_T2[Cc*Cc];
__device__ float g_M [Cc*Cc];
__device__ float g_sum [Cc];
__device__ float g_mean[Cc];
__device__ float g_bias[Cc];
__device__ float g_scal[2];   // [0]=rTr, [1]=sqrt(rTr)

// ---------------------------------------------------------------- helpers
__device__ __forceinline__ uint32_t f2tf(float f) {
    uint32_t u; asm("cvt.rna.tf32.f32 %0, %1;" : "=r"(u) : "f"(f)); return u;
}

__device__ __forceinline__ void mma8(float* d, const uint32_t* a, const uint32_t* b) {
    asm volatile(
        "mma.sync.aligned.m16n8k8.row.col.f32.tf32.tf32.f32 "
        "{%0,%1,%2,%3}, {%4,%5,%6,%7}, {%8,%9}, {%0,%1,%2,%3};\n"
        : "+f"(d[0]), "+f"(d[1]), "+f"(d[2]), "+f"(d[3])
        : "r"(a[0]), "r"(a[1]), "r"(a[2]), "r"(a[3]), "r"(b[0]), "r"(b[1]));
}

// ---------------------------------------------------------------- zero
__global__ void k_zero() {
    int idx = blockIdx.x * blockDim.x + threadIdx.x;
    if (idx < Cc*Cc) g_S[idx] = 0.f;
    if (idx < Cc)    g_sum[idx] = 0.f;
}

// ---------------------------------------------------------------- channel sums
__global__ void k_sums(const float* __restrict__ X) {
    int c = blockIdx.x, b = blockIdx.y;
    const float4* p = (const float4*)(X + ((size_t)b * Cc + c) * HWs);
    float s = 0.f;
    for (int i = threadIdx.x; i < HWs/4; i += 128) {
        float4 v = p[i];
        s += (v.x + v.y) + (v.z + v.w);
    }
    #pragma unroll
    for (int o = 16; o > 0; o >>= 1) s += __shfl_down_sync(0xffffffffu, s, o);
    __shared__ float sm[4];
    if ((threadIdx.x & 31) == 0) sm[threadIdx.x >> 5] = s;
    __syncthreads();
    if (threadIdx.x == 0) atomicAdd(&g_sum[c], sm[0] + sm[1] + sm[2] + sm[3]);
}

// ---------------------------------------------------------------- Gram (tf32 MMA)
// 128x128 tile per (pair, batch), BK=32, 8 warps of 64x32 warp-tiles.
__global__ void __launch_bounds__(256, 2) k_gram(const float* __restrict__ X) {
    int p = blockIdx.x;
    int it = 0, rem = p;
    while (rem >= 4 - it) { rem -= 4 - it; it++; }
    int jt = it + rem;
    int b  = blockIdx.y;

    int i0 = it * 128, j0 = jt * 128;
    const float* Xb = X + (size_t)b * Cc * HWs;

    __shared__ uint32_t As[128 * GP];   // [row 0..127][k 0..31]
    __shared__ uint32_t Bs[128 * GP];

    int tid  = threadIdx.x;
    int lane = tid & 31, warp = tid >> 5;
    int g = lane >> 2, tig = lane & 3;
    int wm = (warp >> 2) * 64;     // warp row base (2 rows of warps)
    int wn = (warp & 3) * 32;      // warp col base (4 cols of warps)

    float acc[4][4][4];
    #pragma unroll
    for (int mt = 0; mt < 4; mt++)
        #pragma unroll
        for (int nt = 0; nt < 4; nt++)
            #pragma unroll
            for (int i = 0; i < 4; i++) acc[mt][nt][i] = 0.f;

    for (int k0 = 0; k0 < HWs; k0 += 32) {
        #pragma unroll
        for (int l = 0; l < 4; l++) {
            int e   = tid + l * 256;          // 1024 float4 slots per tile
            int row = e >> 3;
            int kq  = (e & 7) * 4;
            float4 va = *(const float4*)(Xb + (size_t)(i0 + row) * HWs + k0 + kq);
            *(uint4*)&As[row * GP + kq] =
                make_uint4(f2tf(va.x), f2tf(va.y), f2tf(va.z), f2tf(va.w));
            float4 vb = *(const float4*)(Xb + (size_t)(j0 + row) * HWs + k0 + kq);
            *(uint4*)&Bs[row * GP + kq] =
                make_uint4(f2tf(vb.x), f2tf(vb.y), f2tf(vb.z), f2tf(vb.w));
        }
        __syncthreads();

        #pragma unroll
        for (int ks = 0; ks < 32; ks += 8) {
            uint32_t af[4][4], bf[4][2];
            #pragma unroll
            for (int mt = 0; mt < 4; mt++) {
                int r = wm + mt * 16 + g;
                af[mt][0] = As[r       * GP + ks + tig];
                af[mt][1] = As[(r + 8) * GP + ks + tig];
                af[mt][2] = As[r       * GP + ks + tig + 4];
                af[mt][3] = As[(r + 8) * GP + ks + tig + 4];
            }
            #pragma unroll
            for (int nt = 0; nt < 4; nt++) {
                int c = wn + nt * 8 + g;
                bf[nt][0] = Bs[c * GP + ks + tig];
                bf[nt][1] = Bs[c * GP + ks + tig + 4];
            }
            #pragma unroll
            for (int mt = 0; mt < 4; mt++)
                #pragma unroll
                for (int nt = 0; nt < 4; nt++)
                    mma8(acc[mt][nt], af[mt], bf[nt]);
        }
        __syncthreads();
    }

    bool mirror = (it != jt);
    #pragma unroll
    for (int mt = 0; mt < 4; mt++) {
        int m_ = wm + mt * 16 + g;
        #pragma unroll
        for (int nt = 0; nt < 4; nt++) {
            int n_ = wn + nt * 8 + 2 * tig;
            int gi0 = i0 + m_, gi1 = gi0 + 8;
            int gj0 = j0 + n_, gj1 = gj0 + 1;
            atomicAdd(&g_S[gi0 * Cc + gj0], acc[mt][nt][0]);
            atomicAdd(&g_S[gi0 * Cc + gj1], acc[mt][nt][1]);
            atomicAdd(&g_S[gi1 * Cc + gj0], acc[mt][nt][2]);
            atomicAdd(&g_S[gi1 * Cc + gj1], acc[mt][nt][3]);
            if (mirror) {
                atomicAdd(&g_S[gj0 * Cc + gi0], acc[mt][nt][0]);
                atomicAdd(&g_S[gj1 * Cc + gi0], acc[mt][nt][1]);
                atomicAdd(&g_S[gj0 * Cc + gi1], acc[mt][nt][2]);
                atomicAdd(&g_S[gj1 * Cc + gi1], acc[mt][nt][3]);
            }
        }
    }
}

// ---------------------------------------------------------------- prep
__global__ void k_prep1() {   // 1 block, 512 threads
    int c = threadIdx.x;
    float mean = g_sum[c] * (1.0f / MTOTf);
    g_mean[c] = mean;
    float t = EPSf + g_S[c * Cc + c] * (1.0f / MTOTf) - mean * mean;
    __shared__ float red[16];
    #pragma unroll
    for (int o = 16; o > 0; o >>= 1) t += __shfl_down_sync(0xffffffffu, t, o);
    if ((c & 31) == 0) red[c >> 5] = t;
    __syncthreads();
    if (c < 16) {
        float v = red[c];
        #pragma unroll
        for (int o = 8; o > 0; o >>= 1) v += __shfl_down_sync(0x0000ffffu, v, o);
        if (c == 0) {
            float rtr = 1.0f / v;
            g_scal[0] = rtr;
            g_scal[1] = sqrtf(rtr);
        }
    }
}

__global__ void k_prep2() {   // grid 1024 x 256
    int idx = blockIdx.x * 256 + threadIdx.x;
    int i = idx >> 9, j = idx & 511;
    float v = g_S[idx] * (1.0f / MTOTf) - g_mean[i] * g_mean[j];
    if (i == j) v += EPSf;
    g_SN[idx] = v * g_scal[0];
    g_P[idx]  = (i == j) ? 1.0f : 0.0f;
}

// ---------------------------------------------------------------- 512^3 fp32 GEMM body
__device__ __forceinline__ void gemm512_body(
    const float* __restrict__ A, const float* __restrict__ Bm,
    const float* __restrict__ Cin, float* __restrict__ D,
    float alpha, float beta, const float* __restrict__ alpha_dev,
    int i0, int j0)
{
    __shared__ float As[32][68];
    __shared__ float Bs[32][68];

    float acc[4][4];
    #pragma unroll
    for (int r = 0; r < 4; r++)
        #pragma unroll
        for (int c = 0; c < 4; c++) acc[r][c] = 0.f;

    int tid = threadIdx.x;
    int tx4 = (tid & 15) * 4;
    int ty4 = (tid >> 4) * 4;

    for (int k0 = 0; k0 < Cc; k0 += 32) {
        #pragma unroll
        for (int l = 0; l < 2; l++) {
            int idx = tid + l * 256;
            int row = idx >> 3;
            int kq  = (idx & 7) * 4;
            float4 va = *(const float4*)(A + (size_t)(i0 + row) * Cc + k0 + kq);
            As[kq + 0][row] = va.x; As[kq + 1][row] = va.y;
            As[kq + 2][row] = va.z; As[kq + 3][row] = va.w;
            int krow = idx >> 4;
            int cq   = (idx & 15) * 4;
            *(float4*)&Bs[krow][cq] =
                *(const float4*)(Bm + (size_t)(k0 + krow) * Cc + j0 + cq);
        }
        __syncthreads();
        #pragma unroll
        for (int kk = 0; kk < 32; kk++) {
            float4 av = *(const float4*)&As[kk][ty4];
            float4 bv = *(const float4*)&Bs[kk][tx4];
            float ar[4] = {av.x, av.y, av.z, av.w};
            float br[4] = {bv.x, bv.y, bv.z, bv.w};
            #pragma unroll
            for (int r = 0; r < 4; r++)
                #pragma unroll
                for (int c = 0; c < 4; c++)
                    acc[r][c] += ar[r] * br[c];
        }
        __syncthreads();
    }

    float al = alpha;
    if (alpha_dev) al *= *alpha_dev;
    #pragma unroll
    for (int r = 0; r < 4; r++) {
        int gi = i0 + ty4 + r;
        float4 v;
        v.x = al * acc[r][0]; v.y = al * acc[r][1];
        v.z = al * acc[r][2]; v.w = al * acc[r][3];
        if (Cin) {
            float4 ci = *(const float4*)(Cin + (size_t)gi * Cc + j0 + tx4);
            v.x += beta * ci.x; v.y += beta * ci.y;
            v.z += beta * ci.z; v.w += beta * ci.w;
        }
        *(float4*)(D + (size_t)gi * Cc + j0 + tx4) = v;
    }
}

__global__ void __launch_bounds__(256) k_gemm512(
    const float* __restrict__ A, const float* __restrict__ Bm,
    const float* __restrict__ Cin, float* __restrict__ D,
    float alpha, float beta, const float* __restrict__ alpha_dev)
{
    gemm512_body(A, Bm, Cin, D, alpha, beta, alpha_dev,
                 blockIdx.y * 64, blockIdx.x * 64);
}

// dual: z=0 -> D0 = A@B0, z=1 -> D1 = A@B1  (grid 8,8,2)
__global__ void __launch_bounds__(256) k_gemm512_dual(
    const float* __restrict__ A,
    const float* __restrict__ B0, const float* __restrict__ B1,
    float* __restrict__ D0, float* __restrict__ D1)
{
    gemm512_body(A, blockIdx.z ? B1 : B0, nullptr, blockIdx.z ? D1 : D0,
                 1.0f, 0.0f, nullptr, blockIdx.y * 64, blockIdx.x * 64);
}

// ---------------------------------------------------------------- bias = M @ mean
__global__ void k_bias() {   // grid 64 x 256
    int d = blockIdx.x * 8 + (threadIdx.x >> 5);
    int lane = threadIdx.x & 31;
    float s = 0.f;
    for (int c = lane; c < Cc; c += 32) s += g_M[d * Cc + c] * g_mean[c];
    #pragma unroll
    for (int o = 16; o > 0; o >>= 1) s += __shfl_down_sync(0xffffffffu, s, o);
    if (lane == 0) g_bias[d] = s;
}

// ---------------------------------------------------------------- out = M @ X - bias (tf32 MMA)
// per-batch 512x3136: 128x128 tiles, BK=32, 8 warps of 64x32.
__global__ void __launch_bounds__(256, 2) k_out(const float* __restrict__ X,
                                                float* __restrict__ Out)
{
    int j0 = blockIdx.x * 128;   // hw tile (25, last partial)
    int i0 = blockIdx.y * 128;   // d tile (4)
    int b  = blockIdx.z;

    const float* Xb = X + (size_t)b * Cc * HWs;

    __shared__ uint32_t As[128 * GP];   // M tile  [m][k]
    __shared__ uint32_t Bs[32 * BP];    // X tile  [k][n]

    int tid  = threadIdx.x;
    int lane = tid & 31, warp = tid >> 5;
    int g = lane >> 2, tig = lane & 3;
    int wm = (warp >> 2) * 64;
    int wn = (warp & 3) * 32;

    float acc[4][4][4];
    #pragma unroll
    for (int mt = 0; mt < 4; mt++)
        #pragma unroll
        for (int nt = 0; nt < 4; nt++)
            #pragma unroll
            for (int i = 0; i < 4; i++) acc[mt][nt][i] = 0.f;

    for (int k0 = 0; k0 < Cc; k0 += 32) {
        // A tile: 128 rows x 8 kquads
        #pragma unroll
        for (int l = 0; l < 4; l++) {
            int e   = tid + l * 256;
            int row = e >> 3;
            int kq  = (e & 7) * 4;
            float4 v = *(const float4*)(g_M + (size_t)(i0 + row) * Cc + k0 + kq);
            *(uint4*)&As[row * GP + kq] =
                make_uint4(f2tf(v.x), f2tf(v.y), f2tf(v.z), f2tf(v.w));
        }
        // B tile: 32 krows x 32 nquads
        #pragma unroll
        for (int l = 0; l < 4; l++) {
            int e  = tid + l * 256;
            int kr = e >> 5;
            int nq = (e & 31) * 4;
            int hw = j0 + nq;
            float4 v = make_float4(0.f, 0.f, 0.f, 0.f);
            if (hw < HWs)
                v = *(const float4*)(Xb + (size_t)(k0 + kr) * HWs + hw);
            *(uint4*)&Bs[kr * BP + nq] =
                make_uint4(f2tf(v.x), f2tf(v.y), f2tf(v.z), f2tf(v.w));
        }
        __syncthreads();

        #pragma unroll
        for (int ks = 0; ks < 32; ks += 8) {
            uint32_t af[4][4], bf[4][2];
            #pragma unroll
            for (int mt = 0; mt < 4; mt++) {
                int r = wm + mt * 16 + g;
                af[mt][0] = As[r       * GP + ks + tig];
                af[mt][1] = As[(r + 8) * GP + ks + tig];
                af[mt][2] = As[r       * GP + ks + tig + 4];
                af[mt][3] = As[(r + 8) * GP + ks + tig + 4];
            }
            #pragma unroll
            for (int nt = 0; nt < 4; nt++) {
                int c = wn + nt * 8 + g;
                bf[nt][0] = Bs[(ks + tig)     * BP + c];
                bf[nt][1] = Bs[(ks + tig + 4) * BP + c];
            }
            #pragma unroll
            for (int mt = 0; mt < 4; mt++)
                #pragma unroll
                for (int nt = 0; nt < 4; nt++)
                    mma8(acc[mt][nt], af[mt], bf[nt]);
        }
        __syncthreads();
    }

    #pragma unroll
    for (int mt = 0; mt < 4; mt++) {
        int m_  = wm + mt * 16 + g;
        int gi0 = i0 + m_;
        int gi1 = gi0 + 8;
        float bv0 = g_bias[gi0];
        float bv1 = g_bias[gi1];
        float* orow0 = Out + ((size_t)b * Cc + gi0) * HWs;
        float* orow1 = Out + ((size_t)b * Cc + gi1) * HWs;
        #pragma unroll
        for (int nt = 0; nt < 4; nt++) {
            int col = j0 + wn + nt * 8 + 2 * tig;
            if (col < HWs) {
                float2 v0 = make_float2(acc[mt][nt][0] - bv0, acc[mt][nt][1] - bv0);
                float2 v1 = make_float2(acc[mt][nt][2] - bv1, acc[mt][nt][3] - bv1);
                *(float2*)(orow0 + col) = v0;
                *(float2*)(orow1 + col) = v1;
            }
        }
    }
}

// ---------------------------------------------------------------- launch
extern "C" void kernel_launch(void* const* d_in, const int* in_sizes, int n_in,
                              void* d_out, int out_size)
{
    const float* X   = (const float*)d_in[0];
    const float* rot = (const float*)d_in[1];
    float* Out = (float*)d_out;

    float *pP, *pSN, *pT1, *pT2, *pM, *pScal;
    cudaGetSymbolAddress((void**)&pP,    g_P);
    cudaGetSymbolAddress((void**)&pSN,   g_SN);
    cudaGetSymbolAddress((void**)&pT1,   g_T1);
    cudaGetSymbolAddress((void**)&pT2,   g_T2);
    cudaGetSymbolAddress((void**)&pM,    g_M);
    cudaGetSymbolAddress((void**)&pScal, g_scal);

    k_zero<<<(Cc*Cc + 255) / 256, 256>>>();
    k_sums<<<dim3(Cc, Bb), 128>>>(X);
    k_gram<<<dim3(10, Bb), 256>>>(X);
    k_prep1<<<1, 512>>>();
    k_prep2<<<(Cc*Cc) / 256, 256>>>();

    for (int t = 0; t < NS_ITERS; t++) {
        // T1 = P@P, T2 = P@SN in one launch
        k_gemm512_dual<<<dim3(8, 8, 2), 256>>>(pP, pP, pSN, pT1, pT2);
        // P = 1.5P - 0.5 T1@T2
        k_gemm512<<<dim3(8, 8), 256>>>(pT1, pT2, pP, pP, -0.5f, 1.5f, nullptr);
    }

    // M = sqrt(rTr) * rot @ P
    k_gemm512<<<dim3(8, 8), 256>>>(rot, pP, nullptr, pM, 1.0f, 0.0f, pScal + 1);
    k_bias<<<64, 256>>>();
    k_out<<<dim3(25, 4, Bb), 256>>>(X, Out);
}

// round 13
// speedup vs baseline: 1.5718x; 1.0649x over previous
#include <cuda_runtime.h>
#include <math.h>
#include <stdint.h>

// IterNormRotation: X (32,512,56,56) fp32, rot (1,512,512) fp32, T=10.
//   S = X Xᵀ (Gram over m=B*H*W) via tf32 MMA (+ fused channel sums)
//   Sigma = eps I + S/m - mu muᵀ ; rTr = 1/tr ; SN = Sigma*rTr ; P = I
//   10x NS: P = 1.5P - 0.5 (P@P)@(P@SN)   — compensated tf32 MMA (fp32 fidelity)
//   M = sqrt(rTr) * rot @ P ; bias = M@mu
//   out = M @ X - bias  via tf32 MMA

#define Cc   512
#define Bb   32
#define HWs  3136
#define MTOTf 100352.0f
#define EPSf 1e-5f
#define NS_ITERS 10

#define GP 36     // pitch for [row][k] tiles (k=32)
#define BP 136    // pitch for [k][n] tiles (n=128)
#define TBP 68    // pitch for [k][n] tiles (n=64)

__device__ float g_S [Cc*Cc];
__device__ float g_SN[Cc*Cc];
__device__ float g_P [Cc*Cc];
__device__ float g_T1[Cc*Cc];
__device__ float g_T2[Cc*Cc];
__device__ float g_M [Cc*Cc];
__device__ float g_sum [Cc];
__device__ float g_mean[Cc];
__device__ float g_bias[Cc];
__device__ float g_scal[2];   // [0]=rTr, [1]=sqrt(rTr)

// ---------------------------------------------------------------- helpers
__device__ __forceinline__ uint32_t f2tf(float f) {
    uint32_t u; asm("cvt.rna.tf32.f32 %0, %1;" : "=r"(u) : "f"(f)); return u;
}

__device__ __forceinline__ void mma8(float* d, const uint32_t* a, const uint32_t* b) {
    asm volatile(
        "mma.sync.aligned.m16n8k8.row.col.f32.tf32.tf32.f32 "
        "{%0,%1,%2,%3}, {%4,%5,%6,%7}, {%8,%9}, {%0,%1,%2,%3};\n"
        : "+f"(d[0]), "+f"(d[1]), "+f"(d[2]), "+f"(d[3])
        : "r"(a[0]), "r"(a[1]), "r"(a[2]), "r"(a[3]), "r"(b[0]), "r"(b[1]));
}

// ---------------------------------------------------------------- zero
__global__ void k_zero() {
    int idx = blockIdx.x * blockDim.x + threadIdx.x;
    if (idx < Cc*Cc) g_S[idx] = 0.f;
    if (idx < Cc)    g_sum[idx] = 0.f;
}

// ---------------------------------------------------------------- Gram (tf32 MMA)
// 128x128 tile per (pair, batch), BK=32, 8 warps of 64x32 warp-tiles.
// Diagonal-pair blocks also accumulate per-channel sums (replaces k_sums).
__global__ void __launch_bounds__(256, 2) k_gram(const float* __restrict__ X) {
    int p = blockIdx.x;
    int it = 0, rem = p;
    while (rem >= 4 - it) { rem -= 4 - it; it++; }
    int jt = it + rem;
    int b  = blockIdx.y;
    bool diag = (it == jt);

    int i0 = it * 128, j0 = jt * 128;
    const float* Xb = X + (size_t)b * Cc * HWs;

    __shared__ uint32_t As[128 * GP];   // [row 0..127][k 0..31]
    __shared__ uint32_t Bs[128 * GP];

    int tid  = threadIdx.x;
    int lane = tid & 31, warp = tid >> 5;
    int g = lane >> 2, tig = lane & 3;
    int wm = (warp >> 2) * 64;     // warp row base (2 rows of warps)
    int wn = (warp & 3) * 32;      // warp col base (4 cols of warps)

    float acc[4][4][4];
    #pragma unroll
    for (int mt = 0; mt < 4; mt++)
        #pragma unroll
        for (int nt = 0; nt < 4; nt++)
            #pragma unroll
            for (int i = 0; i < 4; i++) acc[mt][nt][i] = 0.f;

    float rsum[4] = {0.f, 0.f, 0.f, 0.f};

    for (int k0 = 0; k0 < HWs; k0 += 32) {
        #pragma unroll
        for (int l = 0; l < 4; l++) {
            int e   = tid + l * 256;          // 1024 float4 slots per tile
            int row = e >> 3;
            int kq  = (e & 7) * 4;
            float4 va = *(const float4*)(Xb + (size_t)(i0 + row) * HWs + k0 + kq);
            *(uint4*)&As[row * GP + kq] =
                make_uint4(f2tf(va.x), f2tf(va.y), f2tf(va.z), f2tf(va.w));
            if (diag) rsum[l] += (va.x + va.y) + (va.z + va.w);
            float4 vb = *(const float4*)(Xb + (size_t)(j0 + row) * HWs + k0 + kq);
            *(uint4*)&Bs[row * GP + kq] =
                make_uint4(f2tf(vb.x), f2tf(vb.y), f2tf(vb.z), f2tf(vb.w));
        }
        __syncthreads();

        #pragma unroll
        for (int ks = 0; ks < 32; ks += 8) {
            uint32_t af[4][4], bf[4][2];
            #pragma unroll
            for (int mt = 0; mt < 4; mt++) {
                int r = wm + mt * 16 + g;
                af[mt][0] = As[r       * GP + ks + tig];
                af[mt][1] = As[(r + 8) * GP + ks + tig];
                af[mt][2] = As[r       * GP + ks + tig + 4];
                af[mt][3] = As[(r + 8) * GP + ks + tig + 4];
            }
            #pragma unroll
            for (int nt = 0; nt < 4; nt++) {
                int c = wn + nt * 8 + g;
                bf[nt][0] = Bs[c * GP + ks + tig];
                bf[nt][1] = Bs[c * GP + ks + tig + 4];
            }
            #pragma unroll
            for (int mt = 0; mt < 4; mt++)
                #pragma unroll
                for (int nt = 0; nt < 4; nt++)
                    mma8(acc[mt][nt], af[mt], bf[nt]);
        }
        __syncthreads();
    }

    if (diag) {
        #pragma unroll
        for (int l = 0; l < 4; l++) {
            int row = (tid + l * 256) >> 3;
            atomicAdd(&g_sum[i0 + row], rsum[l]);
        }
    }

    bool mirror = !diag;
    #pragma unroll
    for (int mt = 0; mt < 4; mt++) {
        int m_ = wm + mt * 16 + g;
        #pragma unroll
        for (int nt = 0; nt < 4; nt++) {
            int n_ = wn + nt * 8 + 2 * tig;
            int gi0 = i0 + m_, gi1 = gi0 + 8;
            int gj0 = j0 + n_, gj1 = gj0 + 1;
            atomicAdd(&g_S[gi0 * Cc + gj0], acc[mt][nt][0]);
            atomicAdd(&g_S[gi0 * Cc + gj1], acc[mt][nt][1]);
            atomicAdd(&g_S[gi1 * Cc + gj0], acc[mt][nt][2]);
            atomicAdd(&g_S[gi1 * Cc + gj1], acc[mt][nt][3]);
            if (mirror) {
                atomicAdd(&g_S[gj0 * Cc + gi0], acc[mt][nt][0]);
                atomicAdd(&g_S[gj1 * Cc + gi0], acc[mt][nt][1]);
                atomicAdd(&g_S[gj0 * Cc + gi1], acc[mt][nt][2]);
                atomicAdd(&g_S[gj1 * Cc + gi1], acc[mt][nt][3]);
            }
        }
    }
}

// ---------------------------------------------------------------- prep
__global__ void k_prep1() {   // 1 block, 512 threads
    int c = threadIdx.x;
    float mean = g_sum[c] * (1.0f / MTOTf);
    g_mean[c] = mean;
    float t = EPSf + g_S[c * Cc + c] * (1.0f / MTOTf) - mean * mean;
    __shared__ float red[16];
    #pragma unroll
    for (int o = 16; o > 0; o >>= 1) t += __shfl_down_sync(0xffffffffu, t, o);
    if ((c & 31) == 0) red[c >> 5] = t;
    __syncthreads();
    if (c < 16) {
        float v = red[c];
        #pragma unroll
        for (int o = 8; o > 0; o >>= 1) v += __shfl_down_sync(0x0000ffffu, v, o);
        if (c == 0) {
            float rtr = 1.0f / v;
            g_scal[0] = rtr;
            g_scal[1] = sqrtf(rtr);
        }
    }
}

__global__ void k_prep2() {   // grid 1024 x 256
    int idx = blockIdx.x * 256 + threadIdx.x;
    int i = idx >> 9, j = idx & 511;
    float v = g_S[idx] * (1.0f / MTOTf) - g_mean[i] * g_mean[j];
    if (i == j) v += EPSf;
    g_SN[idx] = v * g_scal[0];
    g_P[idx]  = (i == j) ? 1.0f : 0.0f;
}

// ---------------------------------------------------------------- 512^3 compensated tf32 GEMM
// D = alpha*(A@B) + beta*Cin, alpha optionally scaled by *alpha_dev.
// Operands split into tf32 hi + tf32 residual; acc += ah*bh + ah*bl + al*bh
// (effective fp32 precision). Tile 32x64, BK=32, 128 threads (4 warps, each
// 32m x 16n). Grid (8, 16[, 2]).
__device__ __forceinline__ void gemm512t_body(
    const float* __restrict__ A, const float* __restrict__ Bm,
    const float* __restrict__ Cin, float* __restrict__ D,
    float alpha, float beta, const float* __restrict__ alpha_dev,
    int i0, int j0)
{
    __shared__ uint32_t Ah[32 * GP], Al[32 * GP];
    __shared__ uint32_t Bh[32 * TBP], Bl[32 * TBP];

    int tid  = threadIdx.x;
    int lane = tid & 31, warp = tid >> 5;
    int g = lane >> 2, tig = lane & 3;
    int wn = warp * 16;

    float acc[2][2][4];
    #pragma unroll
    for (int mt = 0; mt < 2; mt++)
        #pragma unroll
        for (int nt = 0; nt < 2; nt++)
            #pragma unroll
            for (int i = 0; i < 4; i++) acc[mt][nt][i] = 0.f;

    for (int k0 = 0; k0 < Cc; k0 += 32) {
        // A tile: 32 rows x 8 kquads = 256 float4 slots
        #pragma unroll
        for (int l = 0; l < 2; l++) {
            int e   = tid + l * 128;
            int row = e >> 3;
            int kq  = (e & 7) * 4;
            float4 v = *(const float4*)(A + (size_t)(i0 + row) * Cc + k0 + kq);
            uint4 h, lo;
            h.x = f2tf(v.x); lo.x = f2tf(v.x - __uint_as_float(h.x));
            h.y = f2tf(v.y); lo.y = f2tf(v.y - __uint_as_float(h.y));
            h.z = f2tf(v.z); lo.z = f2tf(v.z - __uint_as_float(h.z));
            h.w = f2tf(v.w); lo.w = f2tf(v.w - __uint_as_float(h.w));
            *(uint4*)&Ah[row * GP + kq] = h;
            *(uint4*)&Al[row * GP + kq] = lo;
        }
        // B tile: 32 krows x 16 nquads = 512 float4 slots
        #pragma unroll
        for (int l = 0; l < 4; l++) {
            int e  = tid + l * 128;
            int kr = e >> 4;
            int nq = (e & 15) * 4;
            float4 v = *(const float4*)(Bm + (size_t)(k0 + kr) * Cc + j0 + nq);
            uint4 h, lo;
            h.x = f2tf(v.x); lo.x = f2tf(v.x - __uint_as_float(h.x));
            h.y = f2tf(v.y); lo.y = f2tf(v.y - __uint_as_float(h.y));
            h.z = f2tf(v.z); lo.z = f2tf(v.z - __uint_as_float(h.z));
            h.w = f2tf(v.w); lo.w = f2tf(v.w - __uint_as_float(h.w));
            *(uint4*)&Bh[kr * TBP + nq] = h;
            *(uint4*)&Bl[kr * TBP + nq] = lo;
        }
        __syncthreads();

        #pragma unroll
        for (int ks = 0; ks < 32; ks += 8) {
            uint32_t ah[2][4], al[2][4], bh[2][2], bl[2][2];
            #pragma unroll
            for (int mt = 0; mt < 2; mt++) {
                int r = mt * 16 + g;
                ah[mt][0] = Ah[r       * GP + ks + tig];
                ah[mt][1] = Ah[(r + 8) * GP + ks + tig];
                ah[mt][2] = Ah[r       * GP + ks + tig + 4];
                ah[mt][3] = Ah[(r + 8) * GP + ks + tig + 4];
                al[mt][0] = Al[r       * GP + ks + tig];
                al[mt][1] = Al[(r + 8) * GP + ks + tig];
                al[mt][2] = Al[r       * GP + ks + tig + 4];
                al[mt][3] = Al[(r + 8) * GP + ks + tig + 4];
            }
            #pragma unroll
            for (int nt = 0; nt < 2; nt++) {
                int c = wn + nt * 8 + g;
                bh[nt][0] = Bh[(ks + tig)     * TBP + c];
                bh[nt][1] = Bh[(ks + tig + 4) * TBP + c];
                bl[nt][0] = Bl[(ks + tig)     * TBP + c];
                bl[nt][1] = Bl[(ks + tig + 4) * TBP + c];
            }
            #pragma unroll
            for (int mt = 0; mt < 2; mt++)
                #pragma unroll
                for (int nt = 0; nt < 2; nt++) {
                    mma8(acc[mt][nt], ah[mt], bh[nt]);
                    mma8(acc[mt][nt], ah[mt], bl[nt]);
                    mma8(acc[mt][nt], al[mt], bh[nt]);
                }
        }
        __syncthreads();
    }

    float al_ = alpha;
    if (alpha_dev) al_ *= *alpha_dev;
    #pragma unroll
    for (int mt = 0; mt < 2; mt++) {
        int gi0 = i0 + mt * 16 + g;
        int gi1 = gi0 + 8;
        #pragma unroll
        for (int nt = 0; nt < 2; nt++) {
            int col = j0 + wn + nt * 8 + 2 * tig;
            float2 v0 = make_float2(al_ * acc[mt][nt][0], al_ * acc[mt][nt][1]);
            float2 v1 = make_float2(al_ * acc[mt][nt][2], al_ * acc[mt][nt][3]);
            if (Cin) {
                float2 c0 = *(const float2*)(Cin + (size_t)gi0 * Cc + col);
                float2 c1 = *(const float2*)(Cin + (size_t)gi1 * Cc + col);
                v0.x += beta * c0.x; v0.y += beta * c0.y;
                v1.x += beta * c1.x; v1.y += beta * c1.y;
            }
            *(float2*)(D + (size_t)gi0 * Cc + col) = v0;
            *(float2*)(D + (size_t)gi1 * Cc + col) = v1;
        }
    }
}

__global__ void __launch_bounds__(128) k_gemm512t(
    const float* __restrict__ A, const float* __restrict__ Bm,
    const float* __restrict__ Cin, float* __restrict__ D,
    float alpha, float beta, const float* __restrict__ alpha_dev)
{
    gemm512t_body(A, Bm, Cin, D, alpha, beta, alpha_dev,
                  blockIdx.y * 32, blockIdx.x * 64);
}

// dual: z=0 -> D0 = A@B0, z=1 -> D1 = A@B1  (grid 8,16,2)
__global__ void __launch_bounds__(128) k_gemm512t_dual(
    const float* __restrict__ A,
    const float* __restrict__ B0, const float* __restrict__ B1,
    float* __restrict__ D0, float* __restrict__ D1)
{
    gemm512t_body(A, blockIdx.z ? B1 : B0, nullptr, blockIdx.z ? D1 : D0,
                  1.0f, 0.0f, nullptr, blockIdx.y * 32, blockIdx.x * 64);
}

// ---------------------------------------------------------------- bias = M @ mean
__global__ void k_bias() {   // grid 64 x 256
    int d = blockIdx.x * 8 + (threadIdx.x >> 5);
    int lane = threadIdx.x & 31;
    float s = 0.f;
    for (int c = lane; c < Cc; c += 32) s += g_M[d * Cc + c] * g_mean[c];
    #pragma unroll
    for (int o = 16; o > 0; o >>= 1) s += __shfl_down_sync(0xffffffffu, s, o);
    if (lane == 0) g_bias[d] = s;
}

// ---------------------------------------------------------------- out = M @ X - bias (tf32 MMA)
// per-batch 512x3136: 128x128 tiles, BK=32, 8 warps of 64x32.
__global__ void __launch_bounds__(256, 2) k_out(const float* __restrict__ X,
                                                float* __restrict__ Out)
{
    int j0 = blockIdx.x * 128;   // hw tile (25, last partial)
    int i0 = blockIdx.y * 128;   // d tile (4)
    int b  = blockIdx.z;

    const float* Xb = X + (size_t)b * Cc * HWs;

    __shared__ uint32_t As[128 * GP];   // M tile  [m][k]
    __shared__ uint32_t Bs[32 * BP];    // X tile  [k][n]

    int tid  = threadIdx.x;
    int lane = tid & 31, warp = tid >> 5;
    int g = lane >> 2, tig = lane & 3;
    int wm = (warp >> 2) * 64;
    int wn = (warp & 3) * 32;

    float acc[4][4][4];
    #pragma unroll
    for (int mt = 0; mt < 4; mt++)
        #pragma unroll
        for (int nt = 0; nt < 4; nt++)
            #pragma unroll
            for (int i = 0; i < 4; i++) acc[mt][nt][i] = 0.f;

    for (int k0 = 0; k0 < Cc; k0 += 32) {
        // A tile: 128 rows x 8 kquads
        #pragma unroll
        for (int l = 0; l < 4; l++) {
            int e   = tid + l * 256;
            int row = e >> 3;
            int kq  = (e & 7) * 4;
            float4 v = *(const float4*)(g_M + (size_t)(i0 + row) * Cc + k0 + kq);
            *(uint4*)&As[row * GP + kq] =
                make_uint4(f2tf(v.x), f2tf(v.y), f2tf(v.z), f2tf(v.w));
        }
        // B tile: 32 krows x 32 nquads
        #pragma unroll
        for (int l = 0; l < 4; l++) {
            int e  = tid + l * 256;
            int kr = e >> 5;
            int nq = (e & 31) * 4;
            int hw = j0 + nq;
            float4 v = make_float4(0.f, 0.f, 0.f, 0.f);
            if (hw < HWs)
                v = *(const float4*)(Xb + (size_t)(k0 + kr) * HWs + hw);
            *(uint4*)&Bs[kr * BP + nq] =
                make_uint4(f2tf(v.x), f2tf(v.y), f2tf(v.z), f2tf(v.w));
        }
        __syncthreads();

        #pragma unroll
        for (int ks = 0; ks < 32; ks += 8) {
            uint32_t af[4][4], bf[4][2];
            #pragma unroll
            for (int mt = 0; mt < 4; mt++) {
                int r = wm + mt * 16 + g;
                af[mt][0] = As[r       * GP + ks + tig];
                af[mt][1] = As[(r + 8) * GP + ks + tig];
                af[mt][2] = As[r       * GP + ks + tig + 4];
                af[mt][3] = As[(r + 8) * GP + ks + tig + 4];
            }
            #pragma unroll
            for (int nt = 0; nt < 4; nt++) {
                int c = wn + nt * 8 + g;
                bf[nt][0] = Bs[(ks + tig)     * BP + c];
                bf[nt][1] = Bs[(ks + tig + 4) * BP + c];
            }
            #pragma unroll
            for (int mt = 0; mt < 4; mt++)
                #pragma unroll
                for (int nt = 0; nt < 4; nt++)
                    mma8(acc[mt][nt], af[mt], bf[nt]);
        }
        __syncthreads();
    }

    #pragma unroll
    for (int mt = 0; mt < 4; mt++) {
        int m_  = wm + mt * 16 + g;
        int gi0 = i0 + m_;
        int gi1 = gi0 + 8;
        float bv0 = g_bias[gi0];
        float bv1 = g_bias[gi1];
        float* orow0 = Out + ((size_t)b * Cc + gi0) * HWs;
        float* orow1 = Out + ((size_t)b * Cc + gi1) * HWs;
        #pragma unroll
        for (int nt = 0; nt < 4; nt++) {
            int col = j0 + wn + nt * 8 + 2 * tig;
            if (col < HWs) {
                float2 v0 = make_float2(acc[mt][nt][0] - bv0, acc[mt][nt][1] - bv0);
                float2 v1 = make_float2(acc[mt][nt][2] - bv1, acc[mt][nt][3] - bv1);
                *(float2*)(orow0 + col) = v0;
                *(float2*)(orow1 + col) = v1;
            }
        }
    }
}

// ---------------------------------------------------------------- launch
extern "C" void kernel_launch(void* const* d_in, const int* in_sizes, int n_in,
                              void* d_out, int out_size)
{
    const float* X   = (const float*)d_in[0];
    const float* rot = (const float*)d_in[1];
    float* Out = (float*)d_out;

    float *pP, *pSN, *pT1, *pT2, *pM, *pScal;
    cudaGetSymbolAddress((void**)&pP,    g_P);
    cudaGetSymbolAddress((void**)&pSN,   g_SN);
    cudaGetSymbolAddress((void**)&pT1,   g_T1);
    cudaGetSymbolAddress((void**)&pT2,   g_T2);
    cudaGetSymbolAddress((void**)&pM,    g_M);
    cudaGetSymbolAddress((void**)&pScal, g_scal);

    k_zero<<<(Cc*Cc + 255) / 256, 256>>>();
    k_gram<<<dim3(10, Bb), 256>>>(X);          // also produces g_sum
    k_prep1<<<1, 512>>>();
    k_prep2<<<(Cc*Cc) / 256, 256>>>();

    for (int t = 0; t < NS_ITERS; t++) {
        // T1 = P@P, T2 = P@SN in one launch (compensated tf32)
        k_gemm512t_dual<<<dim3(8, 16, 2), 128>>>(pP, pP, pSN, pT1, pT2);
        // P = 1.5P - 0.5 T1@T2
        k_gemm512t<<<dim3(8, 16), 128>>>(pT1, pT2, pP, pP, -0.5f, 1.5f, nullptr);
    }

    // M = sqrt(rTr) * rot @ P
    k_gemm512t<<<dim3(8, 16), 128>>>(rot, pP, nullptr, pM, 1.0f, 0.0f, pScal + 1);
    k_bias<<<64, 256>>>();
    k_out<<<dim3(25, 4, Bb), 256>>>(X, Out);
}